// round 4
// baseline (speedup 1.0000x reference)
#include <cuda_runtime.h>

#define BB 2048
#define CC 9605
#define NT 256
#define CAP 1024
#define XTHRESH 2.0f
#define EPSF 1e-8f
#define NEG_INF -3.402823e38f

__device__ float g_partials[BB];

// base * w for one element (mult == 1 baseline term)
__device__ __forceinline__ float term_bw(float xv, float yv) {
    float p = __fdividef(1.0f, 1.0f + __expf(-xv));   // sigmoid
    bool pos = yv > 0.5f;
    float xn   = fminf(1.05f - p, 1.0f);              // xs_neg
    float omxn = fmaxf(p - 0.05f, 0.0f);              // 1 - xs_neg
    float arg  = pos ? fmaxf(p, EPSF) : xn;           // xn >= 0.05 > eps always
    float o2   = omxn * omxn;
    float w    = pos ? (1.0f - p) : (o2 * o2);        // (1-pt)^gamma, gamma = 1 or 4
    return __logf(arg) * w;
}

__global__ __launch_bounds__(NT)
void loss_kernel(const float* __restrict__ x, const float* __restrict__ y,
                 const int* __restrict__ ci, const int* __restrict__ ri,
                 const int* __restrict__ di, const int* __restrict__ wl)
{
    const int row = blockIdx.x;
    const float* __restrict__ xr = x + (size_t)row * CC;
    const float* __restrict__ yr = y + (size_t)row * CC;

    __shared__ float s_cval[CAP];
    __shared__ int   s_cidx[CAP];
    __shared__ int   s_count;
    __shared__ int   s_flags;
    __shared__ float s_rv[NT];
    __shared__ int   s_ri[NT];
    __shared__ int   s_sel[10];
    __shared__ float s_corr;

    const int tid = threadIdx.x;
    if (tid == 0) { s_count = 0; s_flags = 0; s_corr = 0.0f; }
    __syncthreads();

    // per-sample ground-truth whitelist group flags (170 sparse y lookups)
    if (tid < 30) {
        if (yr[ci[tid]] > 0.5f) atomicOr(&s_flags, 1);
    } else if (tid < 100) {
        if (yr[ri[tid - 30]] > 0.5f) atomicOr(&s_flags, 2);
    } else if (tid < 170) {
        if (yr[di[tid - 100]] > 0.5f) atomicOr(&s_flags, 4);
    }

    // main streaming pass: baseline sum + top-k candidate collection
    float acc = 0.0f;
    #pragma unroll 2
    for (int c = tid; c < CC; c += NT) {
        float xv = xr[c];
        float yv = yr[c];
        acc += term_bw(xv, yv);
        if (xv > XTHRESH) {                 // sigmoid monotone: rank by x directly
            int k = atomicAdd(&s_count, 1);
            if (k < CAP) { s_cval[k] = xv; s_cidx[k] = c; }
        }
    }
    __syncthreads();

    const int  cnt = s_count;
    const bool fb  = (cnt < 10) || (cnt > CAP);   // fallback path (never on this data)
    const int  nc  = fb ? 0 : cnt;

    // 10 sequential block-argmax passes (tie -> lower index, matching lax.top_k)
    for (int r = 0; r < 10; r++) {
        float bv = NEG_INF; int bi = 0x7fffffff;
        if (!fb) {
            for (int k = tid; k < nc; k += NT) {
                float v = s_cval[k]; int idx = s_cidx[k];
                if (v > bv || (v == bv && idx < bi)) { bv = v; bi = idx; }
            }
        } else {
            for (int c = tid; c < CC; c += NT) {
                float v = xr[c];
                bool used = false;
                for (int q = 0; q < r; q++) used |= (s_sel[q] == c);
                if (!used && (v > bv || (v == bv && c < bi))) { bv = v; bi = c; }
            }
        }
        s_rv[tid] = bv; s_ri[tid] = bi;
        __syncthreads();
        for (int off = NT / 2; off > 0; off >>= 1) {
            if (tid < off) {
                float ov = s_rv[tid + off]; int oi = s_ri[tid + off];
                if (ov > s_rv[tid] || (ov == s_rv[tid] && oi < s_ri[tid])) {
                    s_rv[tid] = ov; s_ri[tid] = oi;
                }
            }
            __syncthreads();
        }
        if (tid == 0) s_sel[r] = s_ri[0];
        __syncthreads();
        if (!fb) {   // invalidate the selected candidate slot
            int selj = s_sel[r];
            for (int k = tid; k < nc; k += NT)
                if (s_cidx[k] == selj) s_cval[k] = NEG_INF;
        }
        __syncthreads();
    }

    // sequential 10-rank whitelist scan + correction (serial, trivial)
    if (tid == 0) {
        int fl = s_flags;
        bool h1 = fl & 1, h2 = fl & 2, h3 = fl & 4;
        bool only4 = !(h1 || h2 || h3);
        bool found = false;
        float fm[10];
        #pragma unroll
        for (int r = 0; r < 10; r++) {
            int j = s_sel[r];
            int wv = wl[j];
            bool in_map = wv > 0;
            bool in_gt = (wv == 1 && h1) || (wv == 2 && h2) ||
                         (wv == 3 && h3) || (wv == 4 && only4);
            float f = 1.0f;
            if (in_map && only4) f *= 0.5f;                  // ALPHA_OTHER
            if (in_map && !in_gt && !found) f *= 2.0f;       // ALPHA1
            fm[r] = f;
            found = found || (in_map && in_gt);
        }
        float extra = found ? 1.0f : 2.0f;                   // post-scan ALPHA1
        float corr = 0.0f;
        #pragma unroll
        for (int r = 0; r < 10; r++) {
            float m = fm[r] * extra;
            if (m != 1.0f) {
                int j = s_sel[r];
                corr += term_bw(xr[j], yr[j]) * (m - 1.0f);
            }
        }
        s_corr = corr;
    }

    // block sum of baseline accumulators
    s_rv[tid] = acc;
    __syncthreads();
    for (int off = NT / 2; off > 0; off >>= 1) {
        if (tid < off) s_rv[tid] += s_rv[tid + off];
        __syncthreads();
    }
    if (tid == 0) g_partials[row] = s_rv[0] + s_corr;
}

__global__ __launch_bounds__(NT)
void reduce_kernel(float* __restrict__ out)
{
    __shared__ float s[NT];
    float a = 0.0f;
    for (int i = threadIdx.x; i < BB; i += NT) a += g_partials[i];
    s[threadIdx.x] = a;
    __syncthreads();
    for (int off = NT / 2; off > 0; off >>= 1) {
        if (threadIdx.x < off) s[threadIdx.x] += s[threadIdx.x + off];
        __syncthreads();
    }
    if (threadIdx.x == 0) out[0] = -s[0];
}

extern "C" void kernel_launch(void* const* d_in, const int* in_sizes, int n_in,
                              void* d_out, int out_size)
{
    const float* x  = (const float*)d_in[0];
    const float* y  = (const float*)d_in[1];
    const int*   ci = (const int*)d_in[2];
    const int*   ri = (const int*)d_in[3];
    const int*   di = (const int*)d_in[4];
    const int*   wl = (const int*)d_in[5];

    loss_kernel<<<BB, NT>>>(x, y, ci, ri, di, wl);
    reduce_kernel<<<1, NT>>>((float*)d_out);
}

// round 6
// speedup vs baseline: 1.4970x; 1.4970x over previous
#include <cuda_runtime.h>

#define BB 2048
#define CC 9605
#define NT 256
#define NW (NT / 32)
#define NITER 10           // ceil(2401 / 256) — covers max nb
#define CAP 1024
#define XTHRESH 2.0f
#define EPSF 1e-8f
#define NEG_INF -3.402823e38f

__device__ float g_partials[BB];
__device__ int   g_done = 0;

// base * w for one element (mult == 1 baseline term)
__device__ __forceinline__ float term_bw(float xv, float yv) {
    float p = __fdividef(1.0f, 1.0f + __expf(-xv));   // sigmoid
    bool pos = yv > 0.5f;
    float xn   = fminf(1.05f - p, 1.0f);              // xs_neg
    float omxn = fmaxf(p - 0.05f, 0.0f);              // 1 - xs_neg
    float arg  = pos ? fmaxf(p, EPSF) : xn;           // xn >= 0.05 > eps always
    float o2   = omxn * omxn;
    float w    = pos ? (1.0f - p) : (o2 * o2);        // (1-pt)^gamma, gamma = 1 or 4
    return __logf(arg) * w;
}

// monotone float->uint mapping so u64 key max == (max val, then min idx)
__device__ __forceinline__ unsigned long long pack_key(float v, int idx) {
    unsigned u = __float_as_uint(v);
    u = (u & 0x80000000u) ? ~u : (u | 0x80000000u);
    return ((unsigned long long)u << 32) | (unsigned)(0xFFFFFFFFu - (unsigned)idx);
}

__device__ __forceinline__ void push_cand(float v, int c, bool pred, int lane,
                                          int* s_count, float* s_cval, int* s_cidx) {
    unsigned m = __ballot_sync(0xFFFFFFFFu, pred);
    if (m == 0) return;
    int leader = __ffs(m) - 1;
    int base = 0;
    if (lane == leader) base = atomicAdd(s_count, __popc(m));
    base = __shfl_sync(0xFFFFFFFFu, base, leader);
    if (pred) {
        int k = base + __popc(m & ((1u << lane) - 1u));
        if (k < CAP) { s_cval[k] = v; s_cidx[k] = c; }
    }
}

__global__ __launch_bounds__(NT)
void loss_kernel(const float* __restrict__ x, const float* __restrict__ y,
                 const int* __restrict__ ci, const int* __restrict__ ri,
                 const int* __restrict__ di, const int* __restrict__ wl,
                 float* __restrict__ out)
{
    const int row = blockIdx.x;
    const float* __restrict__ xr = x + (size_t)row * CC;
    const float* __restrict__ yr = y + (size_t)row * CC;

    // alignment prologue: row*CC % 4 == row % 4, so peel p elements to reach
    // a 16-byte-aligned float4 body.
    const int p  = (4 - (row & 3)) & 3;       // 0..3 peeled head elements
    const int nb = (CC - p) >> 2;             // aligned float4 count
    const int tail_start = p + 4 * nb;        // CC - tail, tail <= 3

    const float4* __restrict__ x4 = (const float4*)(xr + p);
    const float4* __restrict__ y4 = (const float4*)(yr + p);

    __shared__ float s_cval[CAP];
    __shared__ int   s_cidx[CAP];
    __shared__ int   s_count;
    __shared__ int   s_flags;
    __shared__ float s_wsum[NW];
    __shared__ int   s_sel[10];

    const int tid  = threadIdx.x;
    const int lane = tid & 31;
    const int wid  = tid >> 5;

    if (tid == 0) { s_count = 0; s_flags = 0; }
    __syncthreads();

    // per-sample ground-truth whitelist group flags (170 sparse y lookups)
    if (tid < 30) {
        if (yr[ci[tid]] > 0.5f) atomicOr(&s_flags, 1);
    } else if (tid < 100) {
        if (yr[ri[tid - 30]] > 0.5f) atomicOr(&s_flags, 2);
    } else if (tid < 170) {
        if (yr[di[tid - 100]] > 0.5f) atomicOr(&s_flags, 4);
    }

    // main streaming pass: aligned float4 loads, warps fully active for ballots
    float acc = 0.0f;
    #pragma unroll
    for (int it = 0; it < NITER; it++) {
        int i = tid + it * NT;
        bool ok = i < nb;
        float4 xv = ok ? __ldcs(x4 + i) : make_float4(0.f, 0.f, 0.f, 0.f);
        float4 yv = ok ? __ldcs(y4 + i) : make_float4(0.f, 0.f, 0.f, 0.f);
        if (ok) {
            acc += term_bw(xv.x, yv.x) + term_bw(xv.y, yv.y)
                 + term_bw(xv.z, yv.z) + term_bw(xv.w, yv.w);
        }
        int c0 = p + 4 * i;
        push_cand(xv.x, c0 + 0, ok && xv.x > XTHRESH, lane, &s_count, s_cval, s_cidx);
        push_cand(xv.y, c0 + 1, ok && xv.y > XTHRESH, lane, &s_count, s_cval, s_cidx);
        push_cand(xv.z, c0 + 2, ok && xv.z > XTHRESH, lane, &s_count, s_cval, s_cidx);
        push_cand(xv.w, c0 + 3, ok && xv.w > XTHRESH, lane, &s_count, s_cval, s_cidx);
    }
    // head (p elements) + tail (CC - tail_start elements), each <= 3: thread 0
    if (tid == 0) {
        for (int c = 0; c < p; c++) {
            float xv = xr[c], yv = yr[c];
            acc += term_bw(xv, yv);
            if (xv > XTHRESH) {
                int k = atomicAdd(&s_count, 1);
                if (k < CAP) { s_cval[k] = xv; s_cidx[k] = c; }
            }
        }
        for (int c = tail_start; c < CC; c++) {
            float xv = xr[c], yv = yr[c];
            acc += term_bw(xv, yv);
            if (xv > XTHRESH) {
                int k = atomicAdd(&s_count, 1);
                if (k < CAP) { s_cval[k] = xv; s_cidx[k] = c; }
            }
        }
    }

    // warp partial sums
    #pragma unroll
    for (int o = 16; o > 0; o >>= 1) acc += __shfl_xor_sync(0xFFFFFFFFu, acc, o);
    if (lane == 0) s_wsum[wid] = acc;

    __syncthreads();          // candidates + flags + wsums visible
    if (wid != 0) return;     // warps 1..7 done; warp 0 finishes the row

    const int  cnt = s_count;
    const bool fb  = (cnt < 10) || (cnt > CAP);   // guaranteed-correct slow path

    if (!fb) {
        // 10 argmax passes over ~cnt candidates, u64 keys, warp-only
        for (int r = 0; r < 10; r++) {
            unsigned long long best = 0ull;
            for (int k = lane; k < cnt; k += 32) {
                unsigned long long key = pack_key(s_cval[k], s_cidx[k]);
                if (key > best) best = key;
            }
            #pragma unroll
            for (int o = 16; o > 0; o >>= 1) {
                unsigned long long t = __shfl_xor_sync(0xFFFFFFFFu, best, o);
                if (t > best) best = t;
            }
            int idx = (int)(0xFFFFFFFFu - (unsigned)best);
            if (lane == 0) s_sel[r] = idx;
            for (int k = lane; k < cnt; k += 32)
                if (s_cidx[k] == idx) s_cval[k] = NEG_INF;
            __syncwarp();
        }
    } else {
        // fallback: 10 argmax passes over the full row (slow, never on this data)
        for (int r = 0; r < 10; r++) {
            unsigned long long best = 0ull;
            for (int c = lane; c < CC; c += 32) {
                bool used = false;
                for (int q = 0; q < r; q++) used |= (s_sel[q] == c);
                if (!used) {
                    unsigned long long key = pack_key(xr[c], c);
                    if (key > best) best = key;
                }
            }
            #pragma unroll
            for (int o = 16; o > 0; o >>= 1) {
                unsigned long long t = __shfl_xor_sync(0xFFFFFFFFu, best, o);
                if (t > best) best = t;
            }
            if (lane == 0) s_sel[r] = (int)(0xFFFFFFFFu - (unsigned)best);
            __syncwarp();
        }
    }

    // block sum (8 warp partials) via warp 0
    float bsum = (lane < NW) ? s_wsum[lane] : 0.0f;
    #pragma unroll
    for (int o = 16; o > 0; o >>= 1) bsum += __shfl_xor_sync(0xFFFFFFFFu, bsum, o);

    if (lane == 0) {
        // sequential 10-rank whitelist scan + correction
        int fl = s_flags;
        bool h1 = fl & 1, h2 = fl & 2, h3 = fl & 4;
        bool only4 = !(h1 || h2 || h3);
        bool found = false;
        float fm[10];
        #pragma unroll
        for (int r = 0; r < 10; r++) {
            int j = s_sel[r];
            int wv = wl[j];
            bool in_map = wv > 0;
            bool in_gt = (wv == 1 && h1) || (wv == 2 && h2) ||
                         (wv == 3 && h3) || (wv == 4 && only4);
            float f = 1.0f;
            if (in_map && only4) f *= 0.5f;                  // ALPHA_OTHER
            if (in_map && !in_gt && !found) f *= 2.0f;       // ALPHA1
            fm[r] = f;
            found = found || (in_map && in_gt);
        }
        float extra = found ? 1.0f : 2.0f;                   // post-scan ALPHA1
        float corr = 0.0f;
        #pragma unroll
        for (int r = 0; r < 10; r++) {
            float m = fm[r] * extra;
            if (m != 1.0f) {
                int j = s_sel[r];
                corr += term_bw(xr[j], yr[j]) * (m - 1.0f);
            }
        }
        g_partials[row] = bsum + corr;
    }

    // last block fuses the final reduction (fixed-order -> deterministic)
    int done = 0;
    if (lane == 0) {
        __threadfence();
        done = atomicAdd(&g_done, 1);
    }
    done = __shfl_sync(0xFFFFFFFFu, done, 0);
    if (done == BB - 1) {
        __threadfence();
        float a = 0.0f;
        for (int i = lane; i < BB; i += 32) a += g_partials[i];
        #pragma unroll
        for (int o = 16; o > 0; o >>= 1) a += __shfl_xor_sync(0xFFFFFFFFu, a, o);
        if (lane == 0) {
            out[0] = -a;
            g_done = 0;        // reset for next graph replay
        }
    }
}

extern "C" void kernel_launch(void* const* d_in, const int* in_sizes, int n_in,
                              void* d_out, int out_size)
{
    const float* x  = (const float*)d_in[0];
    const float* y  = (const float*)d_in[1];
    const int*   ci = (const int*)d_in[2];
    const int*   ri = (const int*)d_in[3];
    const int*   di = (const int*)d_in[4];
    const int*   wl = (const int*)d_in[5];

    loss_kernel<<<BB, NT>>>(x, y, ci, ri, di, wl, (float*)d_out);
}

// round 7
// speedup vs baseline: 1.6031x; 1.0709x over previous
#include <cuda_runtime.h>

#define BB 2048
#define CC 9605
#define NT 256
#define NW (NT / 32)
#define CAP 1024
#define XTHRESH 2.0f
#define EPSF 1e-8f
#define NEG_INF -3.402823e38f

__device__ float g_partials[BB];
__device__ int   g_done = 0;

// base * w for one element; y is exactly 0.0f or 1.0f so FFMA blends replace selects
__device__ __forceinline__ float term_bw(float xv, float yv) {
    float p  = __fdividef(1.0f, 1.0f + __expf(-xv));   // sigmoid
    float xn = fminf(1.05f - p, 1.0f);                 // xs_neg
    float o  = fmaxf(p - 0.05f, 0.0f);                 // 1 - xs_neg
    float o2 = o * o;
    float o4 = o2 * o2;                                // (1-pt)^4 (neg)
    float arg = fmaf(yv, fmaxf(p, EPSF) - xn, xn);     // pos ? max(p,eps) : xn
    float w   = fmaf(yv, (1.0f - p) - o4, o4);         // pos ? (1-p) : o4
    return __logf(arg) * w;
}

// monotone float->uint mapping so u64 key max == (max val, then min idx)
__device__ __forceinline__ unsigned long long pack_key(float v, int idx) {
    unsigned u = __float_as_uint(v);
    u = (u & 0x80000000u) ? ~u : (u | 0x80000000u);
    return ((unsigned long long)u << 32) | (unsigned)(0xFFFFFFFFu - (unsigned)idx);
}

__global__ __launch_bounds__(NT)
void loss_kernel(const float* __restrict__ x, const float* __restrict__ y,
                 const int* __restrict__ ci, const int* __restrict__ ri,
                 const int* __restrict__ di, const int* __restrict__ wl,
                 float* __restrict__ out)
{
    const int row = blockIdx.x;
    const float* __restrict__ xr = x + (size_t)row * CC;
    const float* __restrict__ yr = y + (size_t)row * CC;

    // alignment prologue: row*CC % 4 == row % 4 -> peel p head elements
    const int p  = (4 - (row & 3)) & 3;
    const int nb = (CC - p) >> 2;
    const int tail_start = p + 4 * nb;

    const float4* __restrict__ x4 = (const float4*)(xr + p);
    const float4* __restrict__ y4 = (const float4*)(yr + p);

    __shared__ float s_cval[CAP];
    __shared__ int   s_cidx[CAP];
    __shared__ int   s_count;
    __shared__ int   s_flags;
    __shared__ float s_wsum[NW];
    __shared__ int   s_sel[10];

    const int tid  = threadIdx.x;
    const int lane = tid & 31;
    const int wid  = tid >> 5;

    if (tid == 0) { s_count = 0; s_flags = 0; }
    __syncthreads();

    // per-sample ground-truth whitelist group flags (170 sparse y lookups)
    if (tid < 30) {
        if (yr[ci[tid]] > 0.5f) atomicOr(&s_flags, 1);
    } else if (tid < 100) {
        if (yr[ri[tid - 30]] > 0.5f) atomicOr(&s_flags, 2);
    } else if (tid < 170) {
        if (yr[di[tid - 100]] > 0.5f) atomicOr(&s_flags, 4);
    }

    // main streaming pass: software-pipelined aligned float4 loads
    float acc = 0.0f;
    int i = tid;
    bool have = i < nb;
    float4 xa, ya;
    if (have) { xa = __ldcs(x4 + i); ya = __ldcs(y4 + i); }
    while (have) {
        int inext = i + NT;
        bool hnext = inext < nb;
        float4 xb, yb;
        if (hnext) { xb = __ldcs(x4 + inext); yb = __ldcs(y4 + inext); }

        acc += term_bw(xa.x, ya.x) + term_bw(xa.y, ya.y)
             + term_bw(xa.z, ya.z) + term_bw(xa.w, ya.w);

        int nl = (xa.x > XTHRESH) + (xa.y > XTHRESH)
               + (xa.z > XTHRESH) + (xa.w > XTHRESH);
        if (nl) {                                   // rare (~9% of float4s)
            int k = atomicAdd(&s_count, nl);
            int c0 = p + 4 * i;
            if (xa.x > XTHRESH) { if (k < CAP) { s_cval[k] = xa.x; s_cidx[k] = c0;     } k++; }
            if (xa.y > XTHRESH) { if (k < CAP) { s_cval[k] = xa.y; s_cidx[k] = c0 + 1; } k++; }
            if (xa.z > XTHRESH) { if (k < CAP) { s_cval[k] = xa.z; s_cidx[k] = c0 + 2; } k++; }
            if (xa.w > XTHRESH) { if (k < CAP) { s_cval[k] = xa.w; s_cidx[k] = c0 + 3; } }
        }
        xa = xb; ya = yb; i = inext; have = hnext;
    }

    // head (p elems) + tail (<=3 elems): thread 0
    if (tid == 0) {
        for (int c = 0; c < p; c++) {
            float xv = xr[c], yv = yr[c];
            acc += term_bw(xv, yv);
            if (xv > XTHRESH) {
                int k = atomicAdd(&s_count, 1);
                if (k < CAP) { s_cval[k] = xv; s_cidx[k] = c; }
            }
        }
        for (int c = tail_start; c < CC; c++) {
            float xv = xr[c], yv = yr[c];
            acc += term_bw(xv, yv);
            if (xv > XTHRESH) {
                int k = atomicAdd(&s_count, 1);
                if (k < CAP) { s_cval[k] = xv; s_cidx[k] = c; }
            }
        }
    }

    // warp partial sums
    #pragma unroll
    for (int o = 16; o > 0; o >>= 1) acc += __shfl_xor_sync(0xFFFFFFFFu, acc, o);
    if (lane == 0) s_wsum[wid] = acc;

    __syncthreads();          // candidates + flags + wsums visible
    if (wid != 0) return;     // warps 1..7 done; warp 0 finishes the row

    const int  cnt = s_count;
    const bool fb  = (cnt < 10) || (cnt > CAP);   // guaranteed-correct slow path

    if (!fb) {
        // 10 argmax passes over ~cnt candidates, u64 keys, warp-only
        for (int r = 0; r < 10; r++) {
            unsigned long long best = 0ull;
            for (int k = lane; k < cnt; k += 32) {
                unsigned long long key = pack_key(s_cval[k], s_cidx[k]);
                if (key > best) best = key;
            }
            #pragma unroll
            for (int o = 16; o > 0; o >>= 1) {
                unsigned long long t = __shfl_xor_sync(0xFFFFFFFFu, best, o);
                if (t > best) best = t;
            }
            int idx = (int)(0xFFFFFFFFu - (unsigned)best);
            if (lane == 0) s_sel[r] = idx;
            for (int k = lane; k < cnt; k += 32)
                if (s_cidx[k] == idx) s_cval[k] = NEG_INF;
            __syncwarp();
        }
    } else {
        // fallback: 10 argmax passes over the full row (never on this data)
        for (int r = 0; r < 10; r++) {
            unsigned long long best = 0ull;
            for (int c = lane; c < CC; c += 32) {
                bool used = false;
                for (int q = 0; q < r; q++) used |= (s_sel[q] == c);
                if (!used) {
                    unsigned long long key = pack_key(xr[c], c);
                    if (key > best) best = key;
                }
            }
            #pragma unroll
            for (int o = 16; o > 0; o >>= 1) {
                unsigned long long t = __shfl_xor_sync(0xFFFFFFFFu, best, o);
                if (t > best) best = t;
            }
            if (lane == 0) s_sel[r] = (int)(0xFFFFFFFFu - (unsigned)best);
            __syncwarp();
        }
    }

    // block sum (8 warp partials) via warp 0
    float bsum = (lane < NW) ? s_wsum[lane] : 0.0f;
    #pragma unroll
    for (int o = 16; o > 0; o >>= 1) bsum += __shfl_xor_sync(0xFFFFFFFFu, bsum, o);

    if (lane == 0) {
        // sequential 10-rank whitelist scan + correction
        int fl = s_flags;
        bool h1 = fl & 1, h2 = fl & 2, h3 = fl & 4;
        bool only4 = !(h1 || h2 || h3);
        bool found = false;
        float fm[10];
        #pragma unroll
        for (int r = 0; r < 10; r++) {
            int j = s_sel[r];
            int wv = wl[j];
            bool in_map = wv > 0;
            bool in_gt = (wv == 1 && h1) || (wv == 2 && h2) ||
                         (wv == 3 && h3) || (wv == 4 && only4);
            float f = 1.0f;
            if (in_map && only4) f *= 0.5f;                  // ALPHA_OTHER
            if (in_map && !in_gt && !found) f *= 2.0f;       // ALPHA1
            fm[r] = f;
            found = found || (in_map && in_gt);
        }
        float extra = found ? 1.0f : 2.0f;                   // post-scan ALPHA1
        float corr = 0.0f;
        #pragma unroll
        for (int r = 0; r < 10; r++) {
            float m = fm[r] * extra;
            if (m != 1.0f) {
                int j = s_sel[r];
                corr += term_bw(xr[j], yr[j]) * (m - 1.0f);
            }
        }
        g_partials[row] = bsum + corr;
    }

    // last block fuses the final reduction (fixed-order -> deterministic)
    int done = 0;
    if (lane == 0) {
        __threadfence();
        done = atomicAdd(&g_done, 1);
    }
    done = __shfl_sync(0xFFFFFFFFu, done, 0);
    if (done == BB - 1) {
        __threadfence();
        float a = 0.0f;
        for (int k = lane; k < BB; k += 32) a += g_partials[k];
        #pragma unroll
        for (int o = 16; o > 0; o >>= 1) a += __shfl_xor_sync(0xFFFFFFFFu, a, o);
        if (lane == 0) {
            out[0] = -a;
            g_done = 0;        // reset for next graph replay
        }
    }
}

extern "C" void kernel_launch(void* const* d_in, const int* in_sizes, int n_in,
                              void* d_out, int out_size)
{
    const float* x  = (const float*)d_in[0];
    const float* y  = (const float*)d_in[1];
    const int*   ci = (const int*)d_in[2];
    const int*   ri = (const int*)d_in[3];
    const int*   di = (const int*)d_in[4];
    const int*   wl = (const int*)d_in[5];

    loss_kernel<<<BB, NT>>>(x, y, ci, ri, di, wl, (float*)d_out);
}